// round 4
// baseline (speedup 1.0000x reference)
#include <cuda_runtime.h>

// ShortConv1D: causal depthwise conv1d
// x: [B=4, S=4096, D=2048] f32, w: [D, K=4], b: [D]
// out[b,t,d] = b[d] + sum_k w[d,k] * x[b, t+k-(K-1), d]
//
// HBM-bound. Each thread owns 4 contiguous channels (one float4 along D) and
// walks TSTEP consecutive timesteps with a K-1 deep register sliding window
// (read amplification (TSTEP+3)/TSTEP = 1.094).
//
// R3 changes vs R0:
//  - __launch_bounds__(256, 5): cap regs at 51 -> 1280 threads/SM (occupancy
//    41% -> ~51%) to put more loads in flight and cover DRAM latency.
//  - inner loop grouped by 2 with both loads issued before either compute:
//    guarantees MLP>=2 per warp even at the tighter register budget.
//  - __ldcs on x (streamed once), __stcs on y (never re-read): evict-first,
//    keep L2 clean.

constexpr int BATCH = 4;
constexpr int SEQ   = 4096;
constexpr int DIM   = 2048;
constexpr int D4    = DIM / 4;      // 512 float4 per (b,t) row
constexpr int TSTEP = 32;           // timesteps per thread
constexpr int BLOCK = 256;

__device__ __forceinline__ float4 ldcs4(const float4* p) {
    return __ldcs(p);
}

__global__ void __launch_bounds__(BLOCK, 5)
shortconv1d_kernel(const float4* __restrict__ x4,
                   const float4* __restrict__ w4,   // [D] float4: 4 taps of channel d
                   const float4* __restrict__ b4,   // [D4]
                   float4* __restrict__ y4)
{
    const int d4 = blockIdx.x * BLOCK + threadIdx.x;   // 0..511 (grid.x = 2)
    const int t0 = blockIdx.y * TSTEP;                 // grid.y = SEQ/TSTEP = 128
    const int bb = blockIdx.z;                         // grid.z = 4

    // Per-channel taps: w is [D, K] row-major -> taps of channel c are w4[c].
    const int c0 = d4 * 4;
    const float4 wc0 = w4[c0 + 0];
    const float4 wc1 = w4[c0 + 1];
    const float4 wc2 = w4[c0 + 2];
    const float4 wc3 = w4[c0 + 3];
    const float4 bias = b4[d4];

    const float4* xb = x4 + (size_t)bb * SEQ * D4 + d4;
    float4*       yb = y4 + (size_t)bb * SEQ * D4 + d4;

    const float4 zero = make_float4(0.f, 0.f, 0.f, 0.f);

    // Sliding window: h0 = x[t-3], h1 = x[t-2], h2 = x[t-1]
    float4 h0 = (t0 >= 3) ? __ldg(&xb[(size_t)(t0 - 3) * D4]) : zero;
    float4 h1 = (t0 >= 2) ? __ldg(&xb[(size_t)(t0 - 2) * D4]) : zero;
    float4 h2 = (t0 >= 1) ? __ldg(&xb[(size_t)(t0 - 1) * D4]) : zero;

#pragma unroll
    for (int i = 0; i < TSTEP; i += 2) {
        // Batch both loads up front: >=2 LDGs in flight per warp before any
        // dependent FMA.
        const float4 c0v = ldcs4(&xb[(size_t)(t0 + i + 0) * D4]);
        const float4 c1v = ldcs4(&xb[(size_t)(t0 + i + 1) * D4]);

        float4 o0;
        o0.x = bias.x + wc0.x * h0.x + wc0.y * h1.x + wc0.z * h2.x + wc0.w * c0v.x;
        o0.y = bias.y + wc1.x * h0.y + wc1.y * h1.y + wc1.z * h2.y + wc1.w * c0v.y;
        o0.z = bias.z + wc2.x * h0.z + wc2.y * h1.z + wc2.z * h2.z + wc2.w * c0v.z;
        o0.w = bias.w + wc3.x * h0.w + wc3.y * h1.w + wc3.z * h2.w + wc3.w * c0v.w;
        __stcs(&yb[(size_t)(t0 + i + 0) * D4], o0);

        float4 o1;
        o1.x = bias.x + wc0.x * h1.x + wc0.y * h2.x + wc0.z * c0v.x + wc0.w * c1v.x;
        o1.y = bias.y + wc1.x * h1.y + wc1.y * h2.y + wc1.z * c0v.y + wc1.w * c1v.y;
        o1.z = bias.z + wc2.x * h1.z + wc2.y * h2.z + wc2.z * c0v.z + wc2.w * c1v.z;
        o1.w = bias.w + wc3.x * h1.w + wc3.y * h2.w + wc3.z * c0v.w + wc3.w * c1v.w;
        __stcs(&yb[(size_t)(t0 + i + 1) * D4], o1);

        h0 = h2; h1 = c0v; h2 = c1v;
    }
}

extern "C" void kernel_launch(void* const* d_in, const int* in_sizes, int n_in,
                              void* d_out, int out_size)
{
    const float4* x4 = (const float4*)d_in[0];
    const float4* w4 = (const float4*)d_in[1];
    const float4* b4 = (const float4*)d_in[2];
    float4*       y4 = (float4*)d_out;

    dim3 grid(D4 / BLOCK, SEQ / TSTEP, BATCH);
    shortconv1d_kernel<<<grid, BLOCK>>>(x4, w4, b4, y4);
}

// round 5
// speedup vs baseline: 1.0289x; 1.0289x over previous
#include <cuda_runtime.h>

// ShortConv1D: causal depthwise conv1d
// x: [B=4, S=4096, D=2048] f32, w: [D, K=4], b: [D]
// out[b,t,d] = b[d] + sum_k w[d,k] * x[b, t+k-(K-1), d]
//
// HBM-bound. Each thread owns 4 contiguous channels (one float4 along D) and
// walks TSTEP consecutive timesteps with a K-1 deep register sliding window.
//
// R4 design (post-mortem of R3: reg cap + evict-first hints CUT in-flight
// loads and regressed; reverted):
//  - BLOCK=128, TSTEP=64 -> grid = 1024 blocks, 8 blocks/SM (64K regs exactly)
//    => SINGLE wave (1024 <= 148*8), no ragged tail.
//  - halo amp 67/64 = 1.047 (was 35/32 = 1.094): -4.5% read traffic.
//  - inner loop in groups of 4: 4 independent LDG.128 issued before any
//    dependent FMA (MLP>=4/warp), full 64-reg budget, no cache hints.

constexpr int BATCH = 4;
constexpr int SEQ   = 4096;
constexpr int DIM   = 2048;
constexpr int D4    = DIM / 4;      // 512 float4 per (b,t) row
constexpr int TSTEP = 64;           // timesteps per thread
constexpr int BLOCK = 128;

__global__ void __launch_bounds__(BLOCK, 8)
shortconv1d_kernel(const float4* __restrict__ x4,
                   const float4* __restrict__ w4,   // [D] float4: 4 taps of channel d
                   const float4* __restrict__ b4,   // [D4]
                   float4* __restrict__ y4)
{
    const int d4 = blockIdx.x * BLOCK + threadIdx.x;   // 0..511 (grid.x = 4)
    const int t0 = blockIdx.y * TSTEP;                 // grid.y = SEQ/TSTEP = 64
    const int bb = blockIdx.z;                         // grid.z = 4

    // Per-channel taps: w is [D, K] row-major -> taps of channel c are w4[c].
    const int c0 = d4 * 4;
    const float4 wc0 = w4[c0 + 0];
    const float4 wc1 = w4[c0 + 1];
    const float4 wc2 = w4[c0 + 2];
    const float4 wc3 = w4[c0 + 3];
    const float4 bias = b4[d4];

    const float4* xb = x4 + (size_t)bb * SEQ * D4 + d4;
    float4*       yb = y4 + (size_t)bb * SEQ * D4 + d4;

    const float4 zero = make_float4(0.f, 0.f, 0.f, 0.f);

    // Sliding window: h0 = x[t-3], h1 = x[t-2], h2 = x[t-1]
    float4 h0 = (t0 >= 3) ? xb[(size_t)(t0 - 3) * D4] : zero;
    float4 h1 = (t0 >= 2) ? xb[(size_t)(t0 - 2) * D4] : zero;
    float4 h2 = (t0 >= 1) ? xb[(size_t)(t0 - 1) * D4] : zero;

#pragma unroll
    for (int i = 0; i < TSTEP; i += 4) {
        // 4 independent loads issued up front: MLP>=4 per warp before the
        // dependent FMA chain consumes anything.
        const float4 cv0 = xb[(size_t)(t0 + i + 0) * D4];
        const float4 cv1 = xb[(size_t)(t0 + i + 1) * D4];
        const float4 cv2 = xb[(size_t)(t0 + i + 2) * D4];
        const float4 cv3 = xb[(size_t)(t0 + i + 3) * D4];

        float4 o0;
        o0.x = bias.x + wc0.x * h0.x + wc0.y * h1.x + wc0.z * h2.x + wc0.w * cv0.x;
        o0.y = bias.y + wc1.x * h0.y + wc1.y * h1.y + wc1.z * h2.y + wc1.w * cv0.y;
        o0.z = bias.z + wc2.x * h0.z + wc2.y * h1.z + wc2.z * h2.z + wc2.w * cv0.z;
        o0.w = bias.w + wc3.x * h0.w + wc3.y * h1.w + wc3.z * h2.w + wc3.w * cv0.w;
        yb[(size_t)(t0 + i + 0) * D4] = o0;

        float4 o1;
        o1.x = bias.x + wc0.x * h1.x + wc0.y * h2.x + wc0.z * cv0.x + wc0.w * cv1.x;
        o1.y = bias.y + wc1.x * h1.y + wc1.y * h2.y + wc1.z * cv0.y + wc1.w * cv1.y;
        o1.z = bias.z + wc2.x * h1.z + wc2.y * h2.z + wc2.z * cv0.z + wc2.w * cv1.z;
        o1.w = bias.w + wc3.x * h1.w + wc3.y * h2.w + wc3.z * cv0.w + wc3.w * cv1.w;
        yb[(size_t)(t0 + i + 1) * D4] = o1;

        float4 o2;
        o2.x = bias.x + wc0.x * h2.x + wc0.y * cv0.x + wc0.z * cv1.x + wc0.w * cv2.x;
        o2.y = bias.y + wc1.x * h2.y + wc1.y * cv0.y + wc1.z * cv1.y + wc1.w * cv2.y;
        o2.z = bias.z + wc2.x * h2.z + wc2.y * cv0.z + wc2.z * cv1.z + wc2.w * cv2.z;
        o2.w = bias.w + wc3.x * h2.w + wc3.y * cv0.w + wc3.z * cv1.w + wc3.w * cv2.w;
        yb[(size_t)(t0 + i + 2) * D4] = o2;

        float4 o3;
        o3.x = bias.x + wc0.x * cv0.x + wc0.y * cv1.x + wc0.z * cv2.x + wc0.w * cv3.x;
        o3.y = bias.y + wc1.x * cv0.y + wc1.y * cv1.y + wc1.z * cv2.y + wc1.w * cv3.y;
        o3.z = bias.z + wc2.x * cv0.z + wc2.y * cv1.z + wc2.z * cv2.z + wc2.w * cv3.z;
        o3.w = bias.w + wc3.x * cv0.w + wc3.y * cv1.w + wc3.z * cv2.w + wc3.w * cv3.w;
        yb[(size_t)(t0 + i + 3) * D4] = o3;

        h0 = cv1; h1 = cv2; h2 = cv3;
    }
}

extern "C" void kernel_launch(void* const* d_in, const int* in_sizes, int n_in,
                              void* d_out, int out_size)
{
    const float4* x4 = (const float4*)d_in[0];
    const float4* w4 = (const float4*)d_in[1];
    const float4* b4 = (const float4*)d_in[2];
    float4*       y4 = (float4*)d_out;

    dim3 grid(D4 / BLOCK, SEQ / TSTEP, BATCH);
    shortconv1d_kernel<<<grid, BLOCK>>>(x4, w4, b4, y4);
}